// round 12
// baseline (speedup 1.0000x reference)
#include <cuda_runtime.h>
#include <math.h>

#define HID   512
#define LSRC  512
#define NB    128
#define MAXL  128
#define NSYM  64
#define G3    1536   // 3*HID
#define NSTEP (LSRC + MAXL)   // 640 recurrent steps

// ---------------- scratch (static device globals; no runtime allocation) ----------------
__device__ float g_enc_out[(size_t)NB * LSRC * HID];   // [n][l][h]  (134 MB)
__device__ float g_WhhT_enc[HID * G3];                 // [k][c]
__device__ float g_WhhT_dec[HID * G3];
__device__ float g_WihT_dec[HID * G3];
__device__ float g_gi_emb[NSYM * G3];                  // per-symbol decoder input gates (incl. bih)
__device__ float g_WcT[1024 * NSYM];                   // collapsed head, [k][s]
__device__ float g_bc[NSYM];
__device__ float g_qall[(size_t)MAXL * NB * HID];      // decoder hiddens [t][n][h]  (33.5 MB)
__device__ float g_attn[(size_t)NB * MAXL * HID];      // attention ctx  [n][t][h]  (33.5 MB)
__device__ float g_zero[NB * HID];                     // never written -> zeros
// per-group barrier counters, padded to 128 B so each lives in its own L2 line
__device__ unsigned g_barv[16 * 32];

// ---- f32x2 helpers (FFMA2 only reachable via PTX; ptxas never auto-fuses) ----
__device__ __forceinline__ unsigned long long pack2(float a) {
    unsigned long long r;
    asm("mov.b64 %0, {%1, %1};" : "=l"(r) : "f"(a));
    return r;
}
__device__ __forceinline__ unsigned long long pk2(float lo, float hi) {
    unsigned long long r;
    asm("mov.b64 %0, {%1, %2};" : "=l"(r) : "f"(lo), "f"(hi));
    return r;
}
__device__ __forceinline__ void fma2(unsigned long long& acc, unsigned long long w,
                                     unsigned long long a) {
    asm("fma.rn.f32x2 %0, %1, %2, %0;" : "+l"(acc) : "l"(w), "l"(a));
}
__device__ __forceinline__ void unpack2(unsigned long long v, float& lo, float& hi) {
    asm("mov.b64 {%0, %1}, %2;" : "=f"(lo), "=f"(hi) : "l"(v));
}

// ---------------- init kernels ----------------

__global__ void k_bar_reset() {
    if (threadIdx.x < 16 * 32) g_barv[threadIdx.x] = 0u;
}

// transpose (1536,512) -> (512,1536); which: 0 enc_Whh, 1 dec_Whh, 2 dec_Wih
__global__ void k_transpose(const float* __restrict__ in, int which) {
    int idx = blockIdx.x * 256 + threadIdx.x;
    if (idx >= HID * G3) return;
    int k = idx / G3, c = idx - k * G3;
    float v = in[c * HID + k];
    if (which == 0)      g_WhhT_enc[idx] = v;
    else if (which == 1) g_WhhT_dec[idx] = v;
    else                 g_WihT_dec[idx] = v;
}

// WcT[k][s] = sum_o fc_W[s][o] * attn_ff_W[o][k];  grid=1024 (k), block=64 (s)
__global__ void k_wct(const float* __restrict__ ffW, const float* __restrict__ fcW) {
    __shared__ float col[HID];
    int k = blockIdx.x;
    int s = threadIdx.x;
    for (int o = s; o < HID; o += 64) col[o] = ffW[o * 1024 + k];
    __syncthreads();
    const float* fr = fcW + s * HID;
    float acc = 0.f;
    #pragma unroll 4
    for (int o = 0; o < HID; ++o) acc = fmaf(col[o], fr[o], acc);
    g_WcT[k * NSYM + s] = acc;
}

// bc[s] = fc_b[s] + sum_o fc_W[s][o]*attn_ff_b[o];  <<<1,64>>>
__global__ void k_bc(const float* __restrict__ fcW, const float* __restrict__ ffb,
                     const float* __restrict__ fcb) {
    int s = threadIdx.x;
    float acc = fcb[s];
    for (int o = 0; o < HID; ++o) acc = fmaf(fcW[s * HID + o], ffb[o], acc);
    g_bc[s] = acc;
}

// gi_emb[s][c] = dec_bih[c] + sum_h emb[s][h]*dec_Wih[c][h];  grid=64 (s), block=256
__global__ void k_giemb(const float* __restrict__ emb, const float* __restrict__ bih) {
    __shared__ float es[HID];
    int s = blockIdx.x, t = threadIdx.x;
    for (int h = t; h < HID; h += 256) es[h] = emb[s * HID + h];
    __syncthreads();
    float acc[6] = {0.f, 0.f, 0.f, 0.f, 0.f, 0.f};
    for (int k = 0; k < HID; ++k) {
        float e = es[k];
        const float* w = g_WihT_dec + (size_t)k * G3 + t;
        #pragma unroll
        for (int i = 0; i < 6; ++i) acc[i] = fmaf(e, w[256 * i], acc[i]);
    }
    #pragma unroll
    for (int i = 0; i < 6; ++i) {
        int c = t + 256 * i;
        g_gi_emb[s * G3 + c] = acc[i] + bih[c];
    }
}

// ---------------- persistent recurrent GRU kernel: all 640 steps in one launch --------------
// grid = 128 blocks (ALL co-resident: 128 <= 148 SMs, 33 KB smem, 128 thr => wave 1).
// Block identity fixed for the whole run: jt = bx&15 (32 cols), nt = bx>>4 (16 samples).
// DEPENDENCY STRUCTURE: step t+1 of group nt reads only rows n0..n0+15, written by the 16
// blocks sharing that nt. So the step barrier is PER-GROUP (16 blocks), not global: groups
// run fully decoupled, each on its own padded counter (128 B apart -> distinct L2 lines).
// Inner product uses packed fma.rn.f32x2 (FFMA2): 6 fma2/k instead of 12 FFMA -> halves
// the fma-pipe issue floor that binds at 1 warp/SMSP.
__global__ void __launch_bounds__(128) k_gru_persist(
    const float* __restrict__ x,       // (N,2,L)
    const float* __restrict__ Wih,     // (1536,2) encoder input weights
    const float* __restrict__ bih,     // encoder
    const float* __restrict__ ebhh,    // encoder bhh
    const float* __restrict__ dbhh,    // decoder bhh
    const int*   __restrict__ target)
{
    __shared__ float hsh[16][HID + 8];

    const int jt = blockIdx.x & 15, nt = blockIdx.x >> 4;
    const int tid = threadIdx.x, jq = tid & 7, nl = tid >> 3;
    const int j = jt * 32 + jq * 4;
    const int n0 = nt * 16;
    const int n = n0 + nl;
    unsigned* const ctr = &g_barv[nt * 32];

    for (int tt = 0; tt < NSTEP; ++tt) {
        const int mode = (tt < LSRC) ? 0 : 1;
        const int t = mode ? (tt - LSRC) : tt;

        const float* hPrev; size_t hps;
        const float* WT;
        const float* bhh;
        if (mode == 0) {
            WT = g_WhhT_enc; bhh = ebhh;
            if (t == 0) { hPrev = g_zero; hps = HID; }
            else        { hPrev = g_enc_out + (size_t)(t - 1) * HID; hps = (size_t)LSRC * HID; }
        } else {
            WT = g_WhhT_dec; bhh = dbhh;
            if (t == 0) { hPrev = g_enc_out + (size_t)(LSRC - 1) * HID; hps = (size_t)LSRC * HID; }
            else        { hPrev = g_qall + (size_t)(t - 1) * NB * HID; hps = HID; }
        }

        // stage the 16-row h tile (coalesced float4, L2-coherent to dodge stale L1)
        for (int i = tid; i < 16 * (HID / 4); i += 128) {
            int r = i >> 7, c4 = i & 127;
            float4 v = __ldcg((const float4*)(hPrev + (size_t)(n0 + r) * hps + c4 * 4));
            hsh[r][c4 * 4 + 0] = v.x; hsh[r][c4 * 4 + 1] = v.y;
            hsh[r][c4 * 4 + 2] = v.z; hsh[r][c4 * 4 + 3] = v.w;
        }
        __syncthreads();

        // packed accumulators: {lo=j, hi=j+1}, {lo=j+2, hi=j+3} per gate
        unsigned long long aR0 = 0ull, aR1 = 0ull;
        unsigned long long aZ0 = 0ull, aZ1 = 0ull;
        unsigned long long aN0 = 0ull, aN1 = 0ull;

        const float* wbase = WT + j;
        #pragma unroll 4
        for (int k = 0; k < HID; ++k) {
            unsigned long long aa = pack2(hsh[nl][k]);
            const float* wp = wbase + (size_t)k * G3;
            ulonglong2 r2 = *(const ulonglong2*)(wp);
            ulonglong2 z2 = *(const ulonglong2*)(wp + HID);
            ulonglong2 n2 = *(const ulonglong2*)(wp + 2 * HID);
            fma2(aR0, r2.x, aa); fma2(aR1, r2.y, aa);
            fma2(aZ0, z2.x, aa); fma2(aZ1, z2.y, aa);
            fma2(aN0, n2.x, aa); fma2(aN1, n2.y, aa);
        }

        float aR[4], aZ[4], aN[4];
        unpack2(aR0, aR[0], aR[1]); unpack2(aR1, aR[2], aR[3]);
        unpack2(aZ0, aZ[0], aZ[1]); unpack2(aZ1, aZ[2], aZ[3]);
        unpack2(aN0, aN[0], aN[1]); unpack2(aN1, aN[2], aN[3]);

        float x0 = 0.f, x1 = 0.f;
        const float* gp = nullptr;
        if (mode == 0) {
            x0 = x[n * (2 * LSRC) + t];
            x1 = x[n * (2 * LSRC) + LSRC + t];
        } else {
            int tok = (t == 0) ? 0 : target[n * MAXL + t - 1];
            gp = g_gi_emb + (size_t)tok * G3;
        }

        float o4[4];
        #pragma unroll
        for (int qi = 0; qi < 4; ++qi) {
            int c = j + qi;
            float gir, giz, gin;
            if (mode == 0) {
                gir = fmaf(x1, Wih[2 * c + 1],             fmaf(x0, Wih[2 * c],             bih[c]));
                giz = fmaf(x1, Wih[2 * (c + HID) + 1],     fmaf(x0, Wih[2 * (c + HID)],     bih[c + HID]));
                gin = fmaf(x1, Wih[2 * (c + 2 * HID) + 1], fmaf(x0, Wih[2 * (c + 2 * HID)], bih[c + 2 * HID]));
            } else {
                gir = gp[c]; giz = gp[c + HID]; gin = gp[c + 2 * HID];
            }
            float hr = aR[qi] + bhh[c];
            float hz = aZ[qi] + bhh[c + HID];
            float hn = aN[qi] + bhh[c + 2 * HID];
            float r  = 1.f / (1.f + __expf(-(gir + hr)));
            float z  = 1.f / (1.f + __expf(-(giz + hz)));
            float nn = tanhf(fmaf(r, hn, gin));
            float hp = hsh[nl][c];
            o4[qi] = fmaf(z, hp, (1.f - z) * nn);
        }
        float4 o; o.x = o4[0]; o.y = o4[1]; o.z = o4[2]; o.w = o4[3];
        if (mode == 0)
            *(float4*)(g_enc_out + ((size_t)n * LSRC + t) * HID + j) = o;
        else
            *(float4*)(g_qall + (size_t)t * NB * HID + (size_t)n * HID + j) = o;

        // ---- per-group step barrier (16 blocks sharing nt; counters reset each launch) ----
        if (tt < NSTEP - 1) {
            __threadfence();                 // my stores visible device-wide
            __syncthreads();                 // all threads of block fenced before arrive
            if (tid == 0) {
                atomicAdd(ctr, 1u);
                const unsigned want = 16u * (unsigned)(tt + 1);
                while (*(volatile unsigned*)ctr < want) { }
                __threadfence();             // acquire: order spin-read before next step's loads
            }
            __syncthreads();                 // release whole block into next step
        }
    }
}

// ---------------- K1: batched score GEMM  S[n][t][l] = sum_h Q[t][n][h] * E[n][l][h] ----------------
// grid (4 ltiles, 128 n), 256 threads, tile 128t x 128l, k-chunks of 32, micro-tile 8x8.
// Inner loop packed f32x2: 32 FFMA2/k instead of 64 FFMA (pairs along the l axis).
__global__ void __launch_bounds__(256) k_scores(float* __restrict__ S) {
    __shared__ float As[32][132];   // [k][t]
    __shared__ float Bs[32][132];   // [k][l]
    int n = blockIdx.y, l0 = blockIdx.x * 128;
    int tid = threadIdx.x;
    int ty = tid >> 4, tx = tid & 15;
    unsigned long long acc2[8][4];
    #pragma unroll
    for (int i = 0; i < 8; ++i)
        #pragma unroll
        for (int p = 0; p < 4; ++p) acc2[i][p] = 0ull;

    const float* E = g_enc_out + (size_t)n * LSRC * HID;

    for (int k0 = 0; k0 < HID; k0 += 32) {
        #pragma unroll
        for (int i = 0; i < 4; ++i) {
            int idx = i * 256 + tid;              // 0..1023
            int r = idx >> 3, c4 = idx & 7;       // r = t row, c4 = k quad
            float4 v = *(const float4*)(g_qall + (size_t)r * (NB * HID) + (size_t)n * HID + k0 + c4 * 4);
            As[c4 * 4 + 0][r] = v.x; As[c4 * 4 + 1][r] = v.y;
            As[c4 * 4 + 2][r] = v.z; As[c4 * 4 + 3][r] = v.w;
        }
        #pragma unroll
        for (int i = 0; i < 4; ++i) {
            int idx = i * 256 + tid;
            int r = idx >> 3, c4 = idx & 7;       // r = l row
            float4 v = *(const float4*)(E + (size_t)(l0 + r) * HID + k0 + c4 * 4);
            Bs[c4 * 4 + 0][r] = v.x; Bs[c4 * 4 + 1][r] = v.y;
            Bs[c4 * 4 + 2][r] = v.z; Bs[c4 * 4 + 3][r] = v.w;
        }
        __syncthreads();
        #pragma unroll
        for (int k = 0; k < 32; ++k) {
            float4 a0 = *(const float4*)(&As[k][ty * 8]);
            float4 a1 = *(const float4*)(&As[k][ty * 8 + 4]);
            float4 b0 = *(const float4*)(&Bs[k][tx * 8]);
            float4 b1 = *(const float4*)(&Bs[k][tx * 8 + 4]);
            unsigned long long bp[4];
            bp[0] = pk2(b0.x, b0.y); bp[1] = pk2(b0.z, b0.w);
            bp[2] = pk2(b1.x, b1.y); bp[3] = pk2(b1.z, b1.w);
            float a[8] = {a0.x, a0.y, a0.z, a0.w, a1.x, a1.y, a1.z, a1.w};
            #pragma unroll
            for (int i = 0; i < 8; ++i) {
                unsigned long long aa = pack2(a[i]);
                #pragma unroll
                for (int p = 0; p < 4; ++p) fma2(acc2[i][p], bp[p], aa);
            }
        }
        __syncthreads();
    }
    #pragma unroll
    for (int i = 0; i < 8; ++i) {
        int tt = ty * 8 + i;
        float* rowp = S + ((size_t)n * MAXL + tt) * LSRC + l0 + tx * 8;
        float4 o0, o1;
        unpack2(acc2[i][0], o0.x, o0.y); unpack2(acc2[i][1], o0.z, o0.w);
        unpack2(acc2[i][2], o1.x, o1.y); unpack2(acc2[i][3], o1.z, o1.w);
        *(float4*)(rowp) = o0;
        *(float4*)(rowp + 4) = o1;
    }
}

// ---------------- K2: row softmax in place (rows of 512), grid 16384, 128 threads ----------------
__global__ void __launch_bounds__(128) k_softmax(float* __restrict__ W) {
    __shared__ float red[4];
    float* p = W + (size_t)blockIdx.x * LSRC;
    int tid = threadIdx.x, lane = tid & 31, w = tid >> 5;
    float4 v = *(const float4*)(p + tid * 4);
    float m = fmaxf(fmaxf(v.x, v.y), fmaxf(v.z, v.w));
    #pragma unroll
    for (int off = 16; off; off >>= 1) m = fmaxf(m, __shfl_xor_sync(0xffffffffu, m, off));
    if (lane == 0) red[w] = m;
    __syncthreads();
    m = fmaxf(fmaxf(red[0], red[1]), fmaxf(red[2], red[3]));
    __syncthreads();
    float4 e;
    e.x = __expf(v.x - m); e.y = __expf(v.y - m);
    e.z = __expf(v.z - m); e.w = __expf(v.w - m);
    float s = e.x + e.y + e.z + e.w;
    #pragma unroll
    for (int off = 16; off; off >>= 1) s += __shfl_xor_sync(0xffffffffu, s, off);
    if (lane == 0) red[w] = s;
    __syncthreads();
    float inv = 1.f / (red[0] + red[1] + red[2] + red[3]);
    e.x *= inv; e.y *= inv; e.z *= inv; e.w *= inv;
    *(float4*)(p + tid * 4) = e;
}

// ---------------- K3: batched context GEMM  attn[n][t][h] = sum_l W[n][t][l] * E[n][l][h] ----------
// grid (4 htiles, 128 n), 256 threads, tile 128t x 128h, K = 512 (l).  f32x2 inner loop.
__global__ void __launch_bounds__(256) k_attn_gemm(const float* __restrict__ W) {
    __shared__ float As[32][132];   // [k=l][t]
    __shared__ float Bs[32][132];   // [k=l][h]
    int n = blockIdx.y, h0 = blockIdx.x * 128;
    int tid = threadIdx.x;
    int ty = tid >> 4, tx = tid & 15;
    unsigned long long acc2[8][4];
    #pragma unroll
    for (int i = 0; i < 8; ++i)
        #pragma unroll
        for (int p = 0; p < 4; ++p) acc2[i][p] = 0ull;

    const float* E = g_enc_out + (size_t)n * LSRC * HID;
    const float* Wn = W + (size_t)n * MAXL * LSRC;

    for (int k0 = 0; k0 < LSRC; k0 += 32) {
        #pragma unroll
        for (int i = 0; i < 4; ++i) {
            int idx = i * 256 + tid;
            int r = idx >> 3, c4 = idx & 7;       // r = t row, c4 = l quad
            float4 v = *(const float4*)(Wn + (size_t)r * LSRC + k0 + c4 * 4);
            As[c4 * 4 + 0][r] = v.x; As[c4 * 4 + 1][r] = v.y;
            As[c4 * 4 + 2][r] = v.z; As[c4 * 4 + 3][r] = v.w;
        }
        #pragma unroll
        for (int i = 0; i < 4; ++i) {
            int idx = i * 256 + tid;
            int r = idx >> 5, c4 = idx & 31;      // r = l row (32), c4 = h quad (32)
            float4 v = *(const float4*)(E + (size_t)(k0 + r) * HID + h0 + c4 * 4);
            *(float4*)(&Bs[r][c4 * 4]) = v;
        }
        __syncthreads();
        #pragma unroll
        for (int k = 0; k < 32; ++k) {
            float4 a0 = *(const float4*)(&As[k][ty * 8]);
            float4 a1 = *(const float4*)(&As[k][ty * 8 + 4]);
            float4 b0 = *(const float4*)(&Bs[k][tx * 8]);
            float4 b1 = *(const float4*)(&Bs[k][tx * 8 + 4]);
            unsigned long long bp[4];
            bp[0] = pk2(b0.x, b0.y); bp[1] = pk2(b0.z, b0.w);
            bp[2] = pk2(b1.x, b1.y); bp[3] = pk2(b1.z, b1.w);
            float a[8] = {a0.x, a0.y, a0.z, a0.w, a1.x, a1.y, a1.z, a1.w};
            #pragma unroll
            for (int i = 0; i < 8; ++i) {
                unsigned long long aa = pack2(a[i]);
                #pragma unroll
                for (int p = 0; p < 4; ++p) fma2(acc2[i][p], bp[p], aa);
            }
        }
        __syncthreads();
    }
    #pragma unroll
    for (int i = 0; i < 8; ++i) {
        int tt = ty * 8 + i;
        float* rowp = g_attn + ((size_t)n * MAXL + tt) * HID + h0 + tx * 8;
        float4 o0, o1;
        unpack2(acc2[i][0], o0.x, o0.y); unpack2(acc2[i][1], o0.z, o0.w);
        unpack2(acc2[i][2], o1.x, o1.y); unpack2(acc2[i][3], o1.z, o1.w);
        *(float4*)(rowp) = o0;
        *(float4*)(rowp + 4) = o1;
    }
}

// ---------------- K4: output head  v[n][t][s] = concat(q,attn)[n][t][:] @ WcT + bc ----------------
// grid (2 ttiles of 64, 128 n), 256 threads, tile 64t x 64s, K = 1024, micro-tile 4x4.
__global__ void __launch_bounds__(256) k_head(float* __restrict__ vout) {
    __shared__ float As[32][68];    // [k][t]
    __shared__ float Bs[32][68];    // [k][s]
    int n = blockIdx.y, t0 = blockIdx.x * 64;
    int tid = threadIdx.x;
    int ty = tid >> 4, tx = tid & 15;
    float acc[4][4];
    #pragma unroll
    for (int i = 0; i < 4; ++i)
        #pragma unroll
        for (int jj = 0; jj < 4; ++jj) acc[i][jj] = 0.f;

    for (int k0 = 0; k0 < 1024; k0 += 32) {
        #pragma unroll
        for (int i = 0; i < 2; ++i) {
            int idx = i * 256 + tid;              // 0..511
            int r = idx >> 3, c4 = idx & 7;       // r = t row (64), c4 = k quad
            float4 v;
            if (k0 < HID)
                v = *(const float4*)(g_qall + (size_t)(t0 + r) * (NB * HID) + (size_t)n * HID + k0 + c4 * 4);
            else
                v = *(const float4*)(g_attn + ((size_t)n * MAXL + t0 + r) * HID + (k0 - HID) + c4 * 4);
            As[c4 * 4 + 0][r] = v.x; As[c4 * 4 + 1][r] = v.y;
            As[c4 * 4 + 2][r] = v.z; As[c4 * 4 + 3][r] = v.w;
        }
        #pragma unroll
        for (int i = 0; i < 2; ++i) {
            int idx = i * 256 + tid;
            int r = idx >> 4, c4 = idx & 15;      // r = k row (32), c4 = s quad (16)
            float4 v = *(const float4*)(g_WcT + (size_t)(k0 + r) * NSYM + c4 * 4);
            *(float4*)(&Bs[r][c4 * 4]) = v;
        }
        __syncthreads();
        #pragma unroll
        for (int k = 0; k < 32; ++k) {
            float4 a4 = *(const float4*)(&As[k][ty * 4]);
            float4 b4 = *(const float4*)(&Bs[k][tx * 4]);
            float a[4] = {a4.x, a4.y, a4.z, a4.w};
            float b[4] = {b4.x, b4.y, b4.z, b4.w};
            #pragma unroll
            for (int i = 0; i < 4; ++i)
                #pragma unroll
                for (int jj = 0; jj < 4; ++jj) acc[i][jj] = fmaf(a[i], b[jj], acc[i][jj]);
        }
        __syncthreads();
    }
    #pragma unroll
    for (int i = 0; i < 4; ++i) {
        int tt = t0 + ty * 4 + i;
        float4 o;
        o.x = acc[i][0] + g_bc[tx * 4 + 0];
        o.y = acc[i][1] + g_bc[tx * 4 + 1];
        o.z = acc[i][2] + g_bc[tx * 4 + 2];
        o.w = acc[i][3] + g_bc[tx * 4 + 3];
        *(float4*)(vout + ((size_t)n * MAXL + tt) * NSYM + tx * 4) = o;
    }
}

__global__ void k_copy_h(float* __restrict__ out) {
    int i = blockIdx.x * 256 + threadIdx.x;
    if (i < NB * HID) out[i] = g_qall[(size_t)(MAXL - 1) * NB * HID + i];
}

// ---------------- launch ----------------
extern "C" void kernel_launch(void* const* d_in, const int* in_sizes, int n_in,
                              void* d_out, int out_size) {
    const float* x        = (const float*)d_in[0];
    const int*   target   = (const int*)  d_in[1];
    const float* enc_Wih  = (const float*)d_in[2];
    const float* enc_Whh  = (const float*)d_in[3];
    const float* enc_bih  = (const float*)d_in[4];
    const float* enc_bhh  = (const float*)d_in[5];
    const float* dec_Wih  = (const float*)d_in[6];
    const float* dec_Whh  = (const float*)d_in[7];
    const float* dec_bih  = (const float*)d_in[8];
    const float* dec_bhh  = (const float*)d_in[9];
    const float* emb      = (const float*)d_in[10];
    const float* ffW      = (const float*)d_in[11];
    const float* ffb      = (const float*)d_in[12];
    const float* fcW      = (const float*)d_in[13];
    const float* fcb      = (const float*)d_in[14];

    float* out  = (float*)d_out;
    float* vout = out;                                   // (128,128,64)
    float* dech = out + (size_t)NB * MAXL * NSYM;        // (1,128,512)
    float* allw = dech + (size_t)NB * HID;               // (128,128,512)

    const int TG = (HID * G3 + 255) / 256;               // 3072
    k_bar_reset<<<1, 512>>>();
    k_transpose<<<TG, 256>>>(enc_Whh, 0);
    k_transpose<<<TG, 256>>>(dec_Whh, 1);
    k_transpose<<<TG, 256>>>(dec_Wih, 2);
    k_wct<<<1024, 64>>>(ffW, fcW);
    k_bc<<<1, 64>>>(fcW, ffb, fcb);
    k_giemb<<<NSYM, 256>>>(emb, dec_bih);

    // all 640 recurrent steps in ONE persistent kernel (128 co-resident blocks)
    k_gru_persist<<<128, 128>>>(x, enc_Wih, enc_bih, enc_bhh, dec_bhh, target);

    {
        dim3 g1(4, NB);  k_scores<<<g1, 256>>>(allw);
        k_softmax<<<NB * MAXL, 128>>>(allw);
        dim3 g3(4, NB);  k_attn_gemm<<<g3, 256>>>(allw);
        dim3 g4(2, NB);  k_head<<<g4, 256>>>(vout);
    }

    k_copy_h<<<(NB * HID + 255) / 256, 256>>>(dech);
}

// round 16
// speedup vs baseline: 3.0429x; 3.0429x over previous
#include <cuda_runtime.h>
#include <math.h>

#define HID   512
#define LSRC  512
#define NB    128
#define MAXL  128
#define NSYM  64
#define G3    1536   // 3*HID
#define NSTEP (LSRC + MAXL)   // 640 recurrent steps

// dynamic smem layout for k_gru_persist (floats):
//   ws   [512*96]          weight slice for this block's 32 cols x 3 gates, [k][96]
//   hsh  [16][HID+8]       h tile
//   s_bhh[96] s_wx0[96] s_wx1[96] s_bih[96]
#define WS_FLOATS   (512 * 96)
#define HSH_STRIDE  (HID + 8)
#define HSH_FLOATS  (16 * HSH_STRIDE)
#define MISC_FLOATS (4 * 96)
#define SMEM_PERSIST ((WS_FLOATS + HSH_FLOATS + MISC_FLOATS) * 4)   // 231,424 B

// ---------------- scratch (static device globals; no runtime allocation) ----------------
__device__ float g_enc_out[(size_t)NB * LSRC * HID];   // [n][l][h]  (134 MB)
__device__ float g_WhhT_enc[HID * G3];                 // [k][c]
__device__ float g_WhhT_dec[HID * G3];
__device__ float g_WihT_dec[HID * G3];
__device__ float g_gi_emb[NSYM * G3];                  // per-symbol decoder input gates (incl. bih)
__device__ float g_WcT[1024 * NSYM];                   // collapsed head, [k][s]
__device__ float g_bc[NSYM];
__device__ float g_qall[(size_t)MAXL * NB * HID];      // decoder hiddens [t][n][h]  (33.5 MB)
__device__ float g_attn[(size_t)NB * MAXL * HID];      // attention ctx  [n][t][h]  (33.5 MB)
__device__ float g_zero[NB * HID];                     // never written -> zeros
// per-group barrier counters, padded to 128 B so each lives in its own L2 line
__device__ unsigned g_barv[16 * 32];

// ---- f32x2 helpers (FFMA2 only reachable via PTX; ptxas never auto-fuses) ----
__device__ __forceinline__ unsigned long long pack2(float a) {
    unsigned long long r;
    asm("mov.b64 %0, {%1, %1};" : "=l"(r) : "f"(a));
    return r;
}
__device__ __forceinline__ unsigned long long pk2(float lo, float hi) {
    unsigned long long r;
    asm("mov.b64 %0, {%1, %2};" : "=l"(r) : "f"(lo), "f"(hi));
    return r;
}
__device__ __forceinline__ void fma2(unsigned long long& acc, unsigned long long w,
                                     unsigned long long a) {
    asm("fma.rn.f32x2 %0, %1, %2, %0;" : "+l"(acc) : "l"(w), "l"(a));
}
__device__ __forceinline__ void unpack2(unsigned long long v, float& lo, float& hi) {
    asm("mov.b64 {%0, %1}, %2;" : "=f"(lo), "=f"(hi) : "l"(v));
}

// ---------------- init kernels ----------------

__global__ void k_bar_reset() {
    if (threadIdx.x < 16 * 32) g_barv[threadIdx.x] = 0u;
}

// transpose (1536,512) -> (512,1536); which: 0 enc_Whh, 1 dec_Whh, 2 dec_Wih
__global__ void k_transpose(const float* __restrict__ in, int which) {
    int idx = blockIdx.x * 256 + threadIdx.x;
    if (idx >= HID * G3) return;
    int k = idx / G3, c = idx - k * G3;
    float v = in[c * HID + k];
    if (which == 0)      g_WhhT_enc[idx] = v;
    else if (which == 1) g_WhhT_dec[idx] = v;
    else                 g_WihT_dec[idx] = v;
}

// WcT[k][s] = sum_o fc_W[s][o] * attn_ff_W[o][k];  grid=1024 (k), block=64 (s)
__global__ void k_wct(const float* __restrict__ ffW, const float* __restrict__ fcW) {
    __shared__ float col[HID];
    int k = blockIdx.x;
    int s = threadIdx.x;
    for (int o = s; o < HID; o += 64) col[o] = ffW[o * 1024 + k];
    __syncthreads();
    const float* fr = fcW + s * HID;
    float acc = 0.f;
    #pragma unroll 4
    for (int o = 0; o < HID; ++o) acc = fmaf(col[o], fr[o], acc);
    g_WcT[k * NSYM + s] = acc;
}

// bc[s] = fc_b[s] + sum_o fc_W[s][o]*attn_ff_b[o];  <<<1,64>>>
__global__ void k_bc(const float* __restrict__ fcW, const float* __restrict__ ffb,
                     const float* __restrict__ fcb) {
    int s = threadIdx.x;
    float acc = fcb[s];
    for (int o = 0; o < HID; ++o) acc = fmaf(fcW[s * HID + o], ffb[o], acc);
    g_bc[s] = acc;
}

// gi_emb[s][c] = dec_bih[c] + sum_h emb[s][h]*dec_Wih[c][h];  grid=64 (s), block=256
__global__ void k_giemb(const float* __restrict__ emb, const float* __restrict__ bih) {
    __shared__ float es[HID];
    int s = blockIdx.x, t = threadIdx.x;
    for (int h = t; h < HID; h += 256) es[h] = emb[s * HID + h];
    __syncthreads();
    float acc[6] = {0.f, 0.f, 0.f, 0.f, 0.f, 0.f};
    for (int k = 0; k < HID; ++k) {
        float e = es[k];
        const float* w = g_WihT_dec + (size_t)k * G3 + t;
        #pragma unroll
        for (int i = 0; i < 6; ++i) acc[i] = fmaf(e, w[256 * i], acc[i]);
    }
    #pragma unroll
    for (int i = 0; i < 6; ++i) {
        int c = t + 256 * i;
        g_gi_emb[s * G3 + c] = acc[i] + bih[c];
    }
}

// ---------------- persistent recurrent GRU kernel: all 640 steps in one launch --------------
// grid = 128 blocks (ALL co-resident: 128 <= 148 SMs, 226 KB smem => 1 block/SM, wave 1).
// Block identity fixed: jt = bx&15 (32 cols), nt = bx>>4 (16 samples, 8 groups).
// WEIGHTS ARE SMEM-RESIDENT: each block stages its 192 KB Whh slice (plus bias/Wih slices)
// into dynamic shared memory once per mode (restage at tt==LSRC is ordered by the step-
// (LSRC-1) epilogue __syncthreads and the pre-GEMM __syncthreads). Steady state has ZERO
// global loads in the inner product: 3 LDS.128 + 1 LDS + 6 FFMA2 per k -> deterministic,
// fma/crossbar balanced (~12.5 cyc/k at 1 warp/SMSP), immune to L1-thrash / L2 latency.
// Per-step gi/x global loads are PREFETCHED before the inner product so their L2
// latency (~250 cyc; L1 carveout is ~2 KB here) hides under the 6k-cycle GEMM.
// Step barrier is per-group (16 blocks sharing nt), padded counters in distinct L2 lines.
__global__ void __launch_bounds__(128) k_gru_persist(
    const float* __restrict__ x,       // (N,2,L)
    const float* __restrict__ Wih,     // (1536,2) encoder input weights
    const float* __restrict__ bih,     // encoder
    const float* __restrict__ ebhh,    // encoder bhh
    const float* __restrict__ dbhh,    // decoder bhh
    const int*   __restrict__ target)
{
    extern __shared__ float smem_dyn[];
    float* const ws    = smem_dyn;                          // [512][96]
    float* const hshf  = smem_dyn + WS_FLOATS;              // [16][HID+8]
    float* const s_bhh = hshf + HSH_FLOATS;                 // [96]
    float* const s_wx0 = s_bhh + 96;                        // [96]
    float* const s_wx1 = s_wx0 + 96;                        // [96]
    float* const s_bih = s_wx1 + 96;                        // [96]

    const int jt = blockIdx.x & 15, nt = blockIdx.x >> 4;
    const int tid = threadIdx.x, jq = tid & 7, nl = tid >> 3;
    const int j = jt * 32 + jq * 4;
    const int n0 = nt * 16;
    const int n = n0 + nl;
    unsigned* const ctr = &g_barv[nt * 32];

    for (int tt = 0; tt < NSTEP; ++tt) {
        const int mode = (tt < LSRC) ? 0 : 1;
        const int t = mode ? (tt - LSRC) : tt;

        // ---- one-time per-mode staging of this block's weight slice into smem ----
        if (tt == 0 || tt == LSRC) {
            const float* WT = mode ? g_WhhT_dec : g_WhhT_enc;
            for (int idx = tid; idx < 512 * 24; idx += 128) {       // 12288 float4
                int k = idx / 24, r = idx - k * 24;
                int gate = r >> 3, q = r & 7;
                float4 v = *(const float4*)(WT + (size_t)k * G3 + gate * HID + jt * 32 + q * 4);
                *(float4*)(ws + k * 96 + gate * 32 + q * 4) = v;
            }
            const float* bp = mode ? dbhh : ebhh;
            if (tid < 96) {
                int gate = tid >> 5, lc = tid & 31;
                int c = gate * HID + jt * 32 + lc;
                s_bhh[tid] = bp[c];
                if (mode == 0) {
                    s_wx0[tid] = Wih[2 * c];
                    s_wx1[tid] = Wih[2 * c + 1];
                    s_bih[tid] = bih[c];
                }
            }
        }

        // ---- PREFETCH per-step global inputs (drain under the inner product) ----
        float x0 = 0.f, x1 = 0.f;
        float p_gi[12];
        if (mode == 0) {
            x0 = __ldcg(x + n * (2 * LSRC) + t);
            x1 = __ldcg(x + n * (2 * LSRC) + LSRC + t);
        } else {
            int tok = (t == 0) ? 0 : __ldg(target + n * MAXL + t - 1);
            const float* gp = g_gi_emb + (size_t)tok * G3;
            #pragma unroll
            for (int qi = 0; qi < 4; ++qi) {
                int c = j + qi;
                p_gi[qi * 3 + 0] = __ldg(gp + c);
                p_gi[qi * 3 + 1] = __ldg(gp + c + HID);
                p_gi[qi * 3 + 2] = __ldg(gp + c + 2 * HID);
            }
        }

        const float* hPrev; size_t hps;
        if (mode == 0) {
            if (t == 0) { hPrev = g_zero; hps = HID; }
            else        { hPrev = g_enc_out + (size_t)(t - 1) * HID; hps = (size_t)LSRC * HID; }
        } else {
            if (t == 0) { hPrev = g_enc_out + (size_t)(LSRC - 1) * HID; hps = (size_t)LSRC * HID; }
            else        { hPrev = g_qall + (size_t)(t - 1) * NB * HID; hps = HID; }
        }

        // stage the 16-row h tile (coalesced float4, L2-coherent to dodge stale L1)
        for (int i = tid; i < 16 * (HID / 4); i += 128) {
            int r = i >> 7, c4 = i & 127;
            float4 v = __ldcg((const float4*)(hPrev + (size_t)(n0 + r) * hps + c4 * 4));
            float* hr = hshf + r * HSH_STRIDE + c4 * 4;
            hr[0] = v.x; hr[1] = v.y; hr[2] = v.z; hr[3] = v.w;
        }
        __syncthreads();

        // packed accumulators: {lo=j, hi=j+1}, {lo=j+2, hi=j+3} per gate
        unsigned long long aR0 = 0ull, aR1 = 0ull;
        unsigned long long aZ0 = 0ull, aZ1 = 0ull;
        unsigned long long aN0 = 0ull, aN1 = 0ull;

        const float* hrow = hshf + nl * HSH_STRIDE;
        const float* wrow = ws + jq * 4;
        #pragma unroll 4
        for (int k = 0; k < HID; ++k) {
            unsigned long long aa = pack2(hrow[k]);
            const float* wp = wrow + k * 96;
            ulonglong2 r2 = *(const ulonglong2*)(wp);
            ulonglong2 z2 = *(const ulonglong2*)(wp + 32);
            ulonglong2 n2 = *(const ulonglong2*)(wp + 64);
            fma2(aR0, r2.x, aa); fma2(aR1, r2.y, aa);
            fma2(aZ0, z2.x, aa); fma2(aZ1, z2.y, aa);
            fma2(aN0, n2.x, aa); fma2(aN1, n2.y, aa);
        }

        float aR[4], aZ[4], aN[4];
        unpack2(aR0, aR[0], aR[1]); unpack2(aR1, aR[2], aR[3]);
        unpack2(aZ0, aZ[0], aZ[1]); unpack2(aZ1, aZ[2], aZ[3]);
        unpack2(aN0, aN[0], aN[1]); unpack2(aN1, aN[2], aN[3]);

        float o4[4];
        #pragma unroll
        for (int qi = 0; qi < 4; ++qi) {
            int lc = jq * 4 + qi;       // local col 0..31
            int c = j + qi;             // global col
            float gir, giz, gin;
            if (mode == 0) {
                gir = fmaf(x1, s_wx1[lc],      fmaf(x0, s_wx0[lc],      s_bih[lc]));
                giz = fmaf(x1, s_wx1[32 + lc], fmaf(x0, s_wx0[32 + lc], s_bih[32 + lc]));
                gin = fmaf(x1, s_wx1[64 + lc], fmaf(x0, s_wx0[64 + lc], s_bih[64 + lc]));
            } else {
                gir = p_gi[qi * 3 + 0]; giz = p_gi[qi * 3 + 1]; gin = p_gi[qi * 3 + 2];
            }
            float hr = aR[qi] + s_bhh[lc];
            float hz = aZ[qi] + s_bhh[32 + lc];
            float hn = aN[qi] + s_bhh[64 + lc];
            float r  = 1.f / (1.f + __expf(-(gir + hr)));
            float z  = 1.f / (1.f + __expf(-(giz + hz)));
            float nn = tanhf(fmaf(r, hn, gin));
            float hp = hrow[c];
            o4[qi] = fmaf(z, hp, (1.f - z) * nn);
        }
        float4 o; o.x = o4[0]; o.y = o4[1]; o.z = o4[2]; o.w = o4[3];
        if (mode == 0)
            *(float4*)(g_enc_out + ((size_t)n * LSRC + t) * HID + j) = o;
        else
            *(float4*)(g_qall + (size_t)t * NB * HID + (size_t)n * HID + j) = o;

        // ---- per-group step barrier (16 blocks sharing nt; counters reset each launch) ----
        if (tt < NSTEP - 1) {
            __threadfence();                 // my stores visible device-wide
            __syncthreads();                 // all threads of block fenced before arrive
            if (tid == 0) {
                atomicAdd(ctr, 1u);
                const unsigned want = 16u * (unsigned)(tt + 1);
                while (*(volatile unsigned*)ctr < want) { }
                __threadfence();             // acquire: order spin-read before next step's loads
            }
            __syncthreads();                 // release whole block into next step
        }
    }
}

// ---------------- K1: batched score GEMM  S[n][t][l] = sum_h Q[t][n][h] * E[n][l][h] ----------------
// grid (4 ltiles, 128 n), 256 threads, tile 128t x 128l, k-chunks of 32, micro-tile 8x8, f32x2.
__global__ void __launch_bounds__(256) k_scores(float* __restrict__ S) {
    __shared__ float As[32][132];   // [k][t]
    __shared__ float Bs[32][132];   // [k][l]
    int n = blockIdx.y, l0 = blockIdx.x * 128;
    int tid = threadIdx.x;
    int ty = tid >> 4, tx = tid & 15;
    unsigned long long acc2[8][4];
    #pragma unroll
    for (int i = 0; i < 8; ++i)
        #pragma unroll
        for (int p = 0; p < 4; ++p) acc2[i][p] = 0ull;

    const float* E = g_enc_out + (size_t)n * LSRC * HID;

    for (int k0 = 0; k0 < HID; k0 += 32) {
        #pragma unroll
        for (int i = 0; i < 4; ++i) {
            int idx = i * 256 + tid;              // 0..1023
            int r = idx >> 3, c4 = idx & 7;       // r = t row, c4 = k quad
            float4 v = *(const float4*)(g_qall + (size_t)r * (NB * HID) + (size_t)n * HID + k0 + c4 * 4);
            As[c4 * 4 + 0][r] = v.x; As[c4 * 4 + 1][r] = v.y;
            As[c4 * 4 + 2][r] = v.z; As[c4 * 4 + 3][r] = v.w;
        }
        #pragma unroll
        for (int i = 0; i < 4; ++i) {
            int idx = i * 256 + tid;
            int r = idx >> 3, c4 = idx & 7;       // r = l row
            float4 v = *(const float4*)(E + (size_t)(l0 + r) * HID + k0 + c4 * 4);
            Bs[c4 * 4 + 0][r] = v.x; Bs[c4 * 4 + 1][r] = v.y;
            Bs[c4 * 4 + 2][r] = v.z; Bs[c4 * 4 + 3][r] = v.w;
        }
        __syncthreads();
        #pragma unroll
        for (int k = 0; k < 32; ++k) {
            float4 a0 = *(const float4*)(&As[k][ty * 8]);
            float4 a1 = *(const float4*)(&As[k][ty * 8 + 4]);
            float4 b0 = *(const float4*)(&Bs[k][tx * 8]);
            float4 b1 = *(const float4*)(&Bs[k][tx * 8 + 4]);
            unsigned long long bp[4];
            bp[0] = pk2(b0.x, b0.y); bp[1] = pk2(b0.z, b0.w);
            bp[2] = pk2(b1.x, b1.y); bp[3] = pk2(b1.z, b1.w);
            float a[8] = {a0.x, a0.y, a0.z, a0.w, a1.x, a1.y, a1.z, a1.w};
            #pragma unroll
            for (int i = 0; i < 8; ++i) {
                unsigned long long aa = pack2(a[i]);
                #pragma unroll
                for (int p = 0; p < 4; ++p) fma2(acc2[i][p], bp[p], aa);
            }
        }
        __syncthreads();
    }
    #pragma unroll
    for (int i = 0; i < 8; ++i) {
        int tt = ty * 8 + i;
        float* rowp = S + ((size_t)n * MAXL + tt) * LSRC + l0 + tx * 8;
        float4 o0, o1;
        unpack2(acc2[i][0], o0.x, o0.y); unpack2(acc2[i][1], o0.z, o0.w);
        unpack2(acc2[i][2], o1.x, o1.y); unpack2(acc2[i][3], o1.z, o1.w);
        *(float4*)(rowp) = o0;
        *(float4*)(rowp + 4) = o1;
    }
}

// ---------------- K2: row softmax in place (rows of 512), grid 16384, 128 threads ----------------
__global__ void __launch_bounds__(128) k_softmax(float* __restrict__ W) {
    __shared__ float red[4];
    float* p = W + (size_t)blockIdx.x * LSRC;
    int tid = threadIdx.x, lane = tid & 31, w = tid >> 5;
    float4 v = *(const float4*)(p + tid * 4);
    float m = fmaxf(fmaxf(v.x, v.y), fmaxf(v.z, v.w));
    #pragma unroll
    for (int off = 16; off; off >>= 1) m = fmaxf(m, __shfl_xor_sync(0xffffffffu, m, off));
    if (lane == 0) red[w] = m;
    __syncthreads();
    m = fmaxf(fmaxf(red[0], red[1]), fmaxf(red[2], red[3]));
    __syncthreads();
    float4 e;
    e.x = __expf(v.x - m); e.y = __expf(v.y - m);
    e.z = __expf(v.z - m); e.w = __expf(v.w - m);
    float s = e.x + e.y + e.z + e.w;
    #pragma unroll
    for (int off = 16; off; off >>= 1) s += __shfl_xor_sync(0xffffffffu, s, off);
    if (lane == 0) red[w] = s;
    __syncthreads();
    float inv = 1.f / (red[0] + red[1] + red[2] + red[3]);
    e.x *= inv; e.y *= inv; e.z *= inv; e.w *= inv;
    *(float4*)(p + tid * 4) = e;
}

// ---------------- K3: batched context GEMM  attn[n][t][h] = sum_l W[n][t][l] * E[n][l][h] ----------
// grid (4 htiles, 128 n), 256 threads, tile 128t x 128h, K = 512 (l), f32x2 inner loop.
__global__ void __launch_bounds__(256) k_attn_gemm(const float* __restrict__ W) {
    __shared__ float As[32][132];   // [k=l][t]
    __shared__ float Bs[32][132];   // [k=l][h]
    int n = blockIdx.y, h0 = blockIdx.x * 128;
    int tid = threadIdx.x;
    int ty = tid >> 4, tx = tid & 15;
    unsigned long long acc2[8][4];
    #pragma unroll
    for (int i = 0; i < 8; ++i)
        #pragma unroll
        for (int p = 0; p < 4; ++p) acc2[i][p] = 0ull;

    const float* E = g_enc_out + (size_t)n * LSRC * HID;
    const float* Wn = W + (size_t)n * MAXL * LSRC;

    for (int k0 = 0; k0 < LSRC; k0 += 32) {
        #pragma unroll
        for (int i = 0; i < 4; ++i) {
            int idx = i * 256 + tid;
            int r = idx >> 3, c4 = idx & 7;       // r = t row, c4 = l quad
            float4 v = *(const float4*)(Wn + (size_t)r * LSRC + k0 + c4 * 4);
            As[c4 * 4 + 0][r] = v.x; As[c4 * 4 + 1][r] = v.y;
            As[c4 * 4 + 2][r] = v.z; As[c4 * 4 + 3][r] = v.w;
        }
        #pragma unroll
        for (int i = 0; i < 4; ++i) {
            int idx = i * 256 + tid;
            int r = idx >> 5, c4 = idx & 31;      // r = l row (32), c4 = h quad (32)
            float4 v = *(const float4*)(E + (size_t)(k0 + r) * HID + h0 + c4 * 4);
            *(float4*)(&Bs[r][c4 * 4]) = v;
        }
        __syncthreads();
        #pragma unroll
        for (int k = 0; k < 32; ++k) {
            float4 a0 = *(const float4*)(&As[k][ty * 8]);
            float4 a1 = *(const float4*)(&As[k][ty * 8 + 4]);
            float4 b0 = *(const float4*)(&Bs[k][tx * 8]);
            float4 b1 = *(const float4*)(&Bs[k][tx * 8 + 4]);
            unsigned long long bp[4];
            bp[0] = pk2(b0.x, b0.y); bp[1] = pk2(b0.z, b0.w);
            bp[2] = pk2(b1.x, b1.y); bp[3] = pk2(b1.z, b1.w);
            float a[8] = {a0.x, a0.y, a0.z, a0.w, a1.x, a1.y, a1.z, a1.w};
            #pragma unroll
            for (int i = 0; i < 8; ++i) {
                unsigned long long aa = pack2(a[i]);
                #pragma unroll
                for (int p = 0; p < 4; ++p) fma2(acc2[i][p], bp[p], aa);
            }
        }
        __syncthreads();
    }
    #pragma unroll
    for (int i = 0; i < 8; ++i) {
        int tt = ty * 8 + i;
        float* rowp = g_attn + ((size_t)n * MAXL + tt) * HID + h0 + tx * 8;
        float4 o0, o1;
        unpack2(acc2[i][0], o0.x, o0.y); unpack2(acc2[i][1], o0.z, o0.w);
        unpack2(acc2[i][2], o1.x, o1.y); unpack2(acc2[i][3], o1.z, o1.w);
        *(float4*)(rowp) = o0;
        *(float4*)(rowp + 4) = o1;
    }
}

// ---------------- K4: output head  v[n][t][s] = concat(q,attn)[n][t][:] @ WcT + bc ----------------
// grid (2 ttiles of 64, 128 n), 256 threads, tile 64t x 64s, K = 1024, micro-tile 4x4.
__global__ void __launch_bounds__(256) k_head(float* __restrict__ vout) {
    __shared__ float As[32][68];    // [k][t]
    __shared__ float Bs[32][68];    // [k][s]
    int n = blockIdx.y, t0 = blockIdx.x * 64;
    int tid = threadIdx.x;
    int ty = tid >> 4, tx = tid & 15;
    float acc[4][4];
    #pragma unroll
    for (int i = 0; i < 4; ++i)
        #pragma unroll
        for (int jj = 0; jj < 4; ++jj) acc[i][jj] = 0.f;

    for (int k0 = 0; k0 < 1024; k0 += 32) {
        #pragma unroll
        for (int i = 0; i < 2; ++i) {
            int idx = i * 256 + tid;              // 0..511
            int r = idx >> 3, c4 = idx & 7;       // r = t row (64), c4 = k quad
            float4 v;
            if (k0 < HID)
                v = *(const float4*)(g_qall + (size_t)(t0 + r) * (NB * HID) + (size_t)n * HID + k0 + c4 * 4);
            else
                v = *(const float4*)(g_attn + ((size_t)n * MAXL + t0 + r) * HID + (k0 - HID) + c4 * 4);
            As[c4 * 4 + 0][r] = v.x; As[c4 * 4 + 1][r] = v.y;
            As[c4 * 4 + 2][r] = v.z; As[c4 * 4 + 3][r] = v.w;
        }
        #pragma unroll
        for (int i = 0; i < 2; ++i) {
            int idx = i * 256 + tid;
            int r = idx >> 4, c4 = idx & 15;      // r = k row (32), c4 = s quad (16)
            float4 v = *(const float4*)(g_WcT + (size_t)(k0 + r) * NSYM + c4 * 4);
            *(float4*)(&Bs[r][c4 * 4]) = v;
        }
        __syncthreads();
        #pragma unroll
        for (int k = 0; k < 32; ++k) {
            float4 a4 = *(const float4*)(&As[k][ty * 4]);
            float4 b4 = *(const float4*)(&Bs[k][tx * 4]);
            float a[4] = {a4.x, a4.y, a4.z, a4.w};
            float b[4] = {b4.x, b4.y, b4.z, b4.w};
            #pragma unroll
            for (int i = 0; i < 4; ++i)
                #pragma unroll
                for (int jj = 0; jj < 4; ++jj) acc[i][jj] = fmaf(a[i], b[jj], acc[i][jj]);
        }
        __syncthreads();
    }
    #pragma unroll
    for (int i = 0; i < 4; ++i) {
        int tt = t0 + ty * 4 + i;
        float4 o;
        o.x = acc[i][0] + g_bc[tx * 4 + 0];
        o.y = acc[i][1] + g_bc[tx * 4 + 1];
        o.z = acc[i][2] + g_bc[tx * 4 + 2];
        o.w = acc[i][3] + g_bc[tx * 4 + 3];
        *(float4*)(vout + ((size_t)n * MAXL + tt) * NSYM + tx * 4) = o;
    }
}

__global__ void k_copy_h(float* __restrict__ out) {
    int i = blockIdx.x * 256 + threadIdx.x;
    if (i < NB * HID) out[i] = g_qall[(size_t)(MAXL - 1) * NB * HID + i];
}

// ---------------- launch ----------------
extern "C" void kernel_launch(void* const* d_in, const int* in_sizes, int n_in,
                              void* d_out, int out_size) {
    const float* x        = (const float*)d_in[0];
    const int*   target   = (const int*)  d_in[1];
    const float* enc_Wih  = (const float*)d_in[2];
    const float* enc_Whh  = (const float*)d_in[3];
    const float* enc_bih  = (const float*)d_in[4];
    const float* enc_bhh  = (const float*)d_in[5];
    const float* dec_Wih  = (const float*)d_in[6];
    const float* dec_Whh  = (const float*)d_in[7];
    const float* dec_bih  = (const float*)d_in[8];
    const float* dec_bhh  = (const float*)d_in[9];
    const float* emb      = (const float*)d_in[10];
    const float* ffW      = (const float*)d_in[11];
    const float* ffb      = (const float*)d_in[12];
    const float* fcW      = (const float*)d_in[13];
    const float* fcb      = (const float*)d_in[14];

    float* out  = (float*)d_out;
    float* vout = out;                                   // (128,128,64)
    float* dech = out + (size_t)NB * MAXL * NSYM;        // (1,128,512)
    float* allw = dech + (size_t)NB * HID;               // (128,128,512)

    // unconditional (idempotent) — no static guards per harness rules
    cudaFuncSetAttribute(k_gru_persist,
                         cudaFuncAttributeMaxDynamicSharedMemorySize, SMEM_PERSIST);

    const int TG = (HID * G3 + 255) / 256;               // 3072
    // launch order chosen so the -s 5 -c 1 ncu capture lands on k_gru_persist (launch #6)
    k_bar_reset<<<1, 512>>>();                           // 1
    k_transpose<<<TG, 256>>>(enc_Whh, 0);                // 2
    k_transpose<<<TG, 256>>>(dec_Whh, 1);                // 3
    k_transpose<<<TG, 256>>>(dec_Wih, 2);                // 4
    k_giemb<<<NSYM, 256>>>(emb, dec_bih);                // 5

    // all 640 recurrent steps in ONE persistent kernel (128 co-resident blocks)
    k_gru_persist<<<128, 128, SMEM_PERSIST>>>(x, enc_Wih, enc_bih, enc_bhh, dec_bhh, target);  // 6

    k_wct<<<1024, 64>>>(ffW, fcW);                       // 7 (needed only by k_head)
    k_bc<<<1, 64>>>(fcW, ffb, fcb);                      // 8

    {
        dim3 g1(4, NB);  k_scores<<<g1, 256>>>(allw);
        k_softmax<<<NB * MAXL, 128>>>(allw);
        dim3 g3(4, NB);  k_attn_gemm<<<g3, 256>>>(allw);
        dim3 g4(2, NB);  k_head<<<g4, 256>>>(vout);
    }

    k_copy_h<<<(NB * HID + 255) / 256, 256>>>(dech);
}